// round 3
// baseline (speedup 1.0000x reference)
#include <cuda_runtime.h>

#define NN 100000
#define NE 800000
#define NT 384          // edge kernel threads per CTA
#define NBLK 148        // persistent grid

// scratch (allocation-free rule: __device__ globals)
__device__ float g_agg[NN * 32];
__device__ float g_P[NN * 64];   // h_s@W0a + h_d@W0c
__device__ float g_Q[NN * 64];   // h_s@W0b + h_d@W0d + b0

typedef unsigned long long u64;

__device__ __forceinline__ u64 pack2(float x) {
    u64 r;
    asm("mov.b64 %0, {%1, %1};" : "=l"(r) : "f"(x));
    return r;
}
__device__ __forceinline__ u64 pack2f(float a, float b) {
    u64 r;
    asm("mov.b64 %0, {%1, %2};" : "=l"(r) : "f"(a), "f"(b));
    return r;
}
__device__ __forceinline__ void unpack2(u64 v, float& a, float& b) {
    asm("mov.b64 {%0, %1}, %2;" : "=f"(a), "=f"(b) : "l"(v));
}
// packed fp32x2 FMA: d = a*b + d
__device__ __forceinline__ void ffma2(u64& d, u64 a, u64 b) {
    asm("fma.rn.f32x2 %0, %1, %2, %0;" : "+l"(d) : "l"(a), "l"(b));
}
__device__ __forceinline__ u64 add2(u64 a, u64 b) {
    u64 r;
    asm("add.rn.f32x2 %0, %1, %2;" : "=l"(r) : "l"(a), "l"(b));
    return r;
}
__device__ __forceinline__ u64 relu2(u64 v) {
    float a, b;
    unpack2(v, a, b);
    return pack2f(fmaxf(a, 0.f), fmaxf(b, 0.f));
}

// rank-1 update, 64 outputs (32 u64 acc)
__device__ __forceinline__ void rank1_64(float xf, const float* wrow, u64* a0) {
    u64 xa = pack2(xf);
    const ulonglong2* wr = (const ulonglong2*)wrow;
#pragma unroll
    for (int j = 0; j < 16; j++) {
        ulonglong2 w = wr[j];
        ffma2(a0[2 * j],     xa, w.x);
        ffma2(a0[2 * j + 1], xa, w.y);
    }
}
// rank-1 update, 32 outputs (16 u64 acc)
__device__ __forceinline__ void rank1_32(float xf, const float* wrow, u64* a0) {
    u64 xa = pack2(xf);
    const ulonglong2* wr = (const ulonglong2*)wrow;
#pragma unroll
    for (int j = 0; j < 8; j++) {
        ulonglong2 w = wr[j];
        ffma2(a0[2 * j],     xa, w.x);
        ffma2(a0[2 * j + 1], xa, w.y);
    }
}

// ---------------- node precompute: P[n], Q[n]; also zeros g_agg ----------------
__global__ void __launch_bounds__(256)
precompute_kernel(const float* __restrict__ h_s, const float* __restrict__ h_d,
                  const float* __restrict__ w0, const float* __restrict__ b0) {
    __shared__ float s_w0[128 * 64];
    __shared__ float s_b0[64];
    const int tid = threadIdx.x;
    {
        float4* d4 = (float4*)s_w0;
        const float4* s4 = (const float4*)w0;
        for (int i = tid; i < 2048; i += 256) d4[i] = s4[i];
        if (tid < 64) s_b0[tid] = b0[tid];
    }
    __syncthreads();

    int n = blockIdx.x * 256 + tid;
    if (n >= NN) return;

    // zero the scatter buffer for this node
    {
        float4 z = make_float4(0.f, 0.f, 0.f, 0.f);
        float4* ag = (float4*)(g_agg + (size_t)n * 32);
#pragma unroll
        for (int i = 0; i < 8; i++) ag[i] = z;
    }

    u64 P[32], Q[32];
    {
        const ulonglong2* bp = (const ulonglong2*)s_b0;
#pragma unroll
        for (int j = 0; j < 16; j++) {
            ulonglong2 t = bp[j];
            P[2 * j] = 0ull; P[2 * j + 1] = 0ull;
            Q[2 * j] = t.x;  Q[2 * j + 1] = t.y;
        }
    }
    const float4* xs = (const float4*)(h_s + (size_t)n * 32);
    const float4* xd = (const float4*)(h_d + (size_t)n * 32);
#pragma unroll 1
    for (int i = 0; i < 8; i++) {
        float4 a = xs[i];
        const float* wa = s_w0 + (4 * i) * 64;
        const float* wb = s_w0 + (32 + 4 * i) * 64;
        rank1_64(a.x, wa,       P); rank1_64(a.x, wb,       Q);
        rank1_64(a.y, wa + 64,  P); rank1_64(a.y, wb + 64,  Q);
        rank1_64(a.z, wa + 128, P); rank1_64(a.z, wb + 128, Q);
        rank1_64(a.w, wa + 192, P); rank1_64(a.w, wb + 192, Q);
    }
#pragma unroll 1
    for (int i = 0; i < 8; i++) {
        float4 a = xd[i];
        const float* wc = s_w0 + (64 + 4 * i) * 64;
        const float* wd = s_w0 + (96 + 4 * i) * 64;
        rank1_64(a.x, wc,       P); rank1_64(a.x, wd,       Q);
        rank1_64(a.y, wc + 64,  P); rank1_64(a.y, wd + 64,  Q);
        rank1_64(a.z, wc + 128, P); rank1_64(a.z, wd + 128, Q);
        rank1_64(a.w, wc + 192, P); rank1_64(a.w, wd + 192, Q);
    }
    ulonglong2* po = (ulonglong2*)(g_P + (size_t)n * 64);
    ulonglong2* qo = (ulonglong2*)(g_Q + (size_t)n * 64);
#pragma unroll
    for (int j = 0; j < 16; j++) {
        ulonglong2 t; t.x = P[2 * j]; t.y = P[2 * j + 1]; po[j] = t;
        ulonglong2 u; u.x = Q[2 * j]; u.y = Q[2 * j + 1]; qo[j] = u;
    }
}

// ---------------- edge kernel ----------------
// smem (floats): s_w0e [0,2048), s_w1 [2048,6144), s_w2 [6144,8192),
//                s_b1 [8192,8256), s_b2 [8256,8288)
//                s_h (u64) at float offset 8288: NT*32 u64
#define SMEM_BYTES (8288 * 4 + NT * 32 * 8)

__global__ void __launch_bounds__(NT, 1)
edge_kernel(const float* __restrict__ h_d,
            const float* __restrict__ ef, const int* __restrict__ si,
            const int* __restrict__ ri,
            const float* __restrict__ w0,
            const float* __restrict__ w1, const float* __restrict__ b1,
            const float* __restrict__ w2, const float* __restrict__ b2) {
    extern __shared__ float smem[];
    float* s_w0e = smem;
    float* s_w1  = smem + 2048;
    float* s_w2  = smem + 6144;
    float* s_b1  = smem + 8192;
    float* s_b2  = smem + 8256;
    u64*   s_h   = (u64*)(smem + 8288);

    const int tid = threadIdx.x;
    {
        float4* d4 = (float4*)s_w0e;
        const float4* s4 = (const float4*)(w0 + 128 * 64);   // W0e rows
        for (int i = tid; i < 512; i += NT) d4[i] = s4[i];
        d4 = (float4*)s_w1; s4 = (const float4*)w1;
        for (int i = tid; i < 1024; i += NT) d4[i] = s4[i];
        d4 = (float4*)s_w2; s4 = (const float4*)w2;
        for (int i = tid; i < 512; i += NT) d4[i] = s4[i];
        if (tid < 64) s_b1[tid] = b1[tid];
        if (tid < 32) s_b2[tid] = b2[tid];
    }
    __syncthreads();

    u64* myh = s_h + tid;

#pragma unroll 1
    for (int e = blockIdx.x * NT + tid; e < NE; e += NBLK * NT) {
        int s = si[e], r = ri[e];

        // ---------- layer 0: P[s] + Q[r] + ef@W0e ----------
        u64 acc[32];
        {
            const ulonglong2* p = (const ulonglong2*)(g_P + (size_t)s * 64);
            const ulonglong2* q = (const ulonglong2*)(g_Q + (size_t)r * 64);
#pragma unroll
            for (int j = 0; j < 16; j++) {
                ulonglong2 a = p[j], b = q[j];
                acc[2 * j]     = add2(a.x, b.x);
                acc[2 * j + 1] = add2(a.y, b.y);
            }
        }
        {
            const float4* p = (const float4*)(ef + (size_t)e * 32);
            float4 a = p[0];
#pragma unroll 1
            for (int i = 0; i < 8; i++) {
                float4 an = p[(i < 7) ? (i + 1) : 7];
                const float* w = s_w0e + i * 256;
                rank1_64(a.x, w,       acc);
                rank1_64(a.y, w + 64,  acc);
                rank1_64(a.z, w + 128, acc);
                rank1_64(a.w, w + 192, acc);
                a = an;
            }
        }

        // relu -> stage h0 (private column, packed u64; no sync needed)
#pragma unroll
        for (int j = 0; j < 32; j++) myh[j * NT] = relu2(acc[j]);

        // ---------- layer 1 ----------
        u64 acc2[32];
        {
            const ulonglong2* bp = (const ulonglong2*)s_b1;
#pragma unroll
            for (int j = 0; j < 16; j++) {
                ulonglong2 t = bp[j];
                acc2[2 * j] = t.x; acc2[2 * j + 1] = t.y;
            }
        }
#pragma unroll 2
        for (int k = 0; k < 64; k += 2) {
            float x0, x1;
            unpack2(myh[(k >> 1) * NT], x0, x1);
            rank1_64(x0, s_w1 + k * 64,       acc2);
            rank1_64(x1, s_w1 + (k + 1) * 64, acc2);
        }
        // relu -> restage h1
#pragma unroll
        for (int j = 0; j < 32; j++) myh[j * NT] = relu2(acc2[j]);

        // ---------- layer 2 ----------
        u64 acc3[16];
        {
            const ulonglong2* bp = (const ulonglong2*)s_b2;
#pragma unroll
            for (int j = 0; j < 8; j++) {
                ulonglong2 t = bp[j];
                acc3[2 * j] = t.x; acc3[2 * j + 1] = t.y;
            }
        }
#pragma unroll 2
        for (int k = 0; k < 64; k += 2) {
            float x0, x1;
            unpack2(myh[(k >> 1) * NT], x0, x1);
            rank1_32(x0, s_w2 + k * 32,       acc3);
            rank1_32(x1, s_w2 + (k + 1) * 32, acc3);
        }

        // ---------- epilogue: relu(psi) * (h_dj - h_di), scatter-add ----------
        {
            const float4* pi = (const float4*)(h_d + (size_t)s * 32);
            const float4* pj = (const float4*)(h_d + (size_t)r * 32);
            float* out = g_agg + (size_t)r * 32;
#pragma unroll
            for (int q = 0; q < 8; q++) {
                float4 a = pj[q], b = pi[q];
                float lo, hi;
                unpack2(acc3[2 * q], lo, hi);
                atomicAdd(out + 4 * q + 0, fmaxf(lo, 0.f) * (a.x - b.x));
                atomicAdd(out + 4 * q + 1, fmaxf(hi, 0.f) * (a.y - b.y));
                unpack2(acc3[2 * q + 1], lo, hi);
                atomicAdd(out + 4 * q + 2, fmaxf(lo, 0.f) * (a.z - b.z));
                atomicAdd(out + 4 * q + 3, fmaxf(hi, 0.f) * (a.w - b.w));
            }
        }
    }
}

// out[n] = h_d_prev[n] + agg[n] @ W   (one thread per node, FFMA2 rank-1)
__global__ void __launch_bounds__(256)
final_kernel(const float* __restrict__ h_d, const float* __restrict__ W,
             float* __restrict__ out) {
    __shared__ float sW[1024];
    int tid = threadIdx.x;
    {
        float4* d4 = (float4*)sW;
        const float4* s4 = (const float4*)W;
        for (int i = tid; i < 256; i += 256) d4[i] = s4[i];
    }
    __syncthreads();
    int n = blockIdx.x * 256 + tid;
    if (n >= NN) return;

    u64 acc[16];
    {
        const ulonglong2* hp = (const ulonglong2*)(h_d + (size_t)n * 32);
#pragma unroll
        for (int j = 0; j < 8; j++) {
            ulonglong2 t = hp[j];
            acc[2 * j] = t.x; acc[2 * j + 1] = t.y;
        }
    }
    const float4* ap = (const float4*)(g_agg + (size_t)n * 32);
#pragma unroll
    for (int i = 0; i < 8; i++) {
        float4 a = ap[i];
        rank1_32(a.x, sW + (4 * i) * 32,     acc);
        rank1_32(a.y, sW + (4 * i + 1) * 32, acc);
        rank1_32(a.z, sW + (4 * i + 2) * 32, acc);
        rank1_32(a.w, sW + (4 * i + 3) * 32, acc);
    }
    ulonglong2* op = (ulonglong2*)(out + (size_t)n * 32);
#pragma unroll
    for (int j = 0; j < 8; j++) {
        ulonglong2 t; t.x = acc[2 * j]; t.y = acc[2 * j + 1];
        op[j] = t;
    }
}

extern "C" void kernel_launch(void* const* d_in, const int* in_sizes, int n_in,
                              void* d_out, int out_size) {
    const float* h_d = (const float*)d_in[0];
    const float* h_s = (const float*)d_in[1];
    const float* ef  = (const float*)d_in[2];
    const int*   si  = (const int*)d_in[3];
    const int*   ri  = (const int*)d_in[4];
    const float* w0  = (const float*)d_in[5];
    const float* b0  = (const float*)d_in[6];
    const float* w1  = (const float*)d_in[7];
    const float* b1  = (const float*)d_in[8];
    const float* w2  = (const float*)d_in[9];
    const float* b2  = (const float*)d_in[10];
    const float* W   = (const float*)d_in[11];
    float* out = (float*)d_out;

    cudaFuncSetAttribute(edge_kernel, cudaFuncAttributeMaxDynamicSharedMemorySize,
                         SMEM_BYTES);

    precompute_kernel<<<(NN + 255) / 256, 256>>>(h_s, h_d, w0, b0);
    edge_kernel<<<NBLK, NT, SMEM_BYTES>>>(h_d, ef, si, ri, w0, w1, b1, w2, b2);
    final_kernel<<<(NN + 255) / 256, 256>>>(h_d, W, out);
}

// round 4
// speedup vs baseline: 1.7434x; 1.7434x over previous
#include <cuda_runtime.h>
#include <cstdint>

#define NN 100000
#define NE 800000
#define NBLK 148
#define ET 384          // edge kernel threads (12 warps)
#define STR 68          // h-staging row stride in u64 (conflict-free)

typedef unsigned long long u64;
typedef unsigned int u32;

// scratch (allocation-free rule: __device__ globals)
__device__ float g_agg[NN * 32];
__device__ float g_P[NN * 64];          // h_s@W0a + h_d@W0c   (exact fp32)
__device__ float g_Q[NN * 64];          // h_s@W0b + h_d@W0d + b0
__device__ ulonglong2 g_Ball[4096];     // fragment-ordered (hi|lo) weight pairs

// ---------------- packed fp32x2 helpers (precompute/final kernels) ----------------
__device__ __forceinline__ u64 pack2(float x) {
    u64 r; asm("mov.b64 %0, {%1, %1};" : "=l"(r) : "f"(x)); return r;
}
__device__ __forceinline__ void ffma2(u64& d, u64 a, u64 b) {
    asm("fma.rn.f32x2 %0, %1, %2, %0;" : "+l"(d) : "l"(a), "l"(b));
}
// rank-1 update, 64 outputs (32 u64 acc)
__device__ __forceinline__ void rank1_64(float xf, const float* wrow, u64* a0) {
    u64 xa = pack2(xf);
    const ulonglong2* wr = (const ulonglong2*)wrow;
#pragma unroll
    for (int j = 0; j < 16; j++) {
        ulonglong2 w = wr[j];
        ffma2(a0[2 * j],     xa, w.x);
        ffma2(a0[2 * j + 1], xa, w.y);
    }
}
// rank-1 update, 32 outputs (16 u64 acc)
__device__ __forceinline__ void rank1_32(float xf, const float* wrow, u64* a0) {
    u64 xa = pack2(xf);
    const ulonglong2* wr = (const ulonglong2*)wrow;
#pragma unroll
    for (int j = 0; j < 8; j++) {
        ulonglong2 w = wr[j];
        ffma2(a0[2 * j],     xa, w.x);
        ffma2(a0[2 * j + 1], xa, w.y);
    }
}

// ---------------- tf32 helpers ----------------
__device__ __forceinline__ void split_tf32(float x, u32& hi, u32& lo) {
    asm("cvt.rna.tf32.f32 %0, %1;" : "=r"(hi) : "f"(x));
    float r = x - __uint_as_float(hi);
    asm("cvt.rna.tf32.f32 %0, %1;" : "=r"(lo) : "f"(r));
}
__device__ __forceinline__ u64 relu_split_pack(float x) {
    float v = fmaxf(x, 0.f);
    u32 h, l;
    split_tf32(v, h, l);
    return (u64)h | ((u64)l << 32);
}
__device__ __forceinline__ void mma_(float c[4], const u32 a[4], u32 b0, u32 b1) {
    asm volatile(
        "mma.sync.aligned.m16n8k8.row.col.f32.tf32.tf32.f32 "
        "{%0,%1,%2,%3}, {%4,%5,%6,%7}, {%8,%9}, {%0,%1,%2,%3};"
        : "+f"(c[0]), "+f"(c[1]), "+f"(c[2]), "+f"(c[3])
        : "r"(a[0]), "r"(a[1]), "r"(a[2]), "r"(a[3]), "r"(b0), "r"(b1));
}
// one K-chunk of a compensated GEMM across NTC n-tiles
template <int NTC>
__device__ __forceinline__ void gemm_step(float C[][4], const u32 ah[4], const u32 al[4],
                                          const ulonglong2* sB, int kc, int Kc, int lane) {
    u32 bh[NTC][2], bl[NTC][2];
#pragma unroll
    for (int nt = 0; nt < NTC; nt++) {
        ulonglong2 t = sB[(nt * Kc + kc) * 32 + lane];
        bh[nt][0] = (u32)t.x; bl[nt][0] = (u32)(t.x >> 32);
        bh[nt][1] = (u32)t.y; bl[nt][1] = (u32)(t.y >> 32);
    }
#pragma unroll
    for (int nt = 0; nt < NTC; nt++) mma_(C[nt], ah, bh[nt][0], bh[nt][1]);
#pragma unroll
    for (int nt = 0; nt < NTC; nt++) mma_(C[nt], ah, bl[nt][0], bl[nt][1]);
#pragma unroll
    for (int nt = 0; nt < NTC; nt++) mma_(C[nt], al, bh[nt][0], bh[nt][1]);
}
__device__ __forceinline__ void red2(float* p, float x, float y) {
    asm volatile("red.global.add.v2.f32 [%0], {%1,%2};" :: "l"(p), "f"(x), "f"(y) : "memory");
}

// ---------------- setup: weights -> fragment-ordered (hi|lo) pairs ----------------
// entry i = fe*32 + lane.  fe<32: W0e (8nt x 4kc); fe in [32,96): W1 (8nt x 8kc);
// fe in [96,128): W2 (4nt x 8kc).  b0 = W[k0][n], b1 = W[k0+4][n].
__global__ void setup_kernel(const float* __restrict__ w0, const float* __restrict__ w1,
                             const float* __restrict__ w2) {
    int i = blockIdx.x * 256 + threadIdx.x;
    if (i >= 4096) return;
    int lane = i & 31, fe = i >> 5;
    const float* W;
    int n, k0, stride;
    if (fe < 32) {
        int nt = fe >> 2, kc = fe & 3;
        n = nt * 8 + (lane >> 2); k0 = kc * 8 + (lane & 3);
        W = w0 + 128 * 64; stride = 64;
    } else if (fe < 96) {
        int f = fe - 32; int nt = f >> 3, kc = f & 7;
        n = nt * 8 + (lane >> 2); k0 = kc * 8 + (lane & 3);
        W = w1; stride = 64;
    } else {
        int f = fe - 96; int nt = f >> 3, kc = f & 7;
        n = nt * 8 + (lane >> 2); k0 = kc * 8 + (lane & 3);
        W = w2; stride = 32;
    }
    float v0 = W[(size_t)k0 * stride + n];
    float v1 = W[(size_t)(k0 + 4) * stride + n];
    u32 h0, l0, h1, l1;
    split_tf32(v0, h0, l0);
    split_tf32(v1, h1, l1);
    ulonglong2 t;
    t.x = (u64)h0 | ((u64)l0 << 32);
    t.y = (u64)h1 | ((u64)l1 << 32);
    g_Ball[i] = t;
}

// ---------------- node precompute: P or Q per warp-half; zeros g_agg ----------------
__global__ void __launch_bounds__(256)
precompute_kernel(const float* __restrict__ h_s, const float* __restrict__ h_d,
                  const float* __restrict__ w0, const float* __restrict__ b0) {
    __shared__ float s_w0[128 * 64];
    __shared__ float s_b0[64];
    const int tid = threadIdx.x;
    {
        float4* d4 = (float4*)s_w0;
        const float4* s4 = (const float4*)w0;
        for (int i = tid; i < 2048; i += 256) d4[i] = s4[i];
        if (tid < 64) s_b0[tid] = b0[tid];
    }
    __syncthreads();

    // warp-uniform half: warps 0,2,4,6 -> P; 1,3,5,7 -> Q; same node range per pair
    int half = (tid >> 5) & 1;
    int n = blockIdx.x * 128 + ((tid >> 6) << 5) + (tid & 31);
    if (n >= NN) return;

    u64 A[32];
    if (half) {
        const ulonglong2* bp = (const ulonglong2*)s_b0;
#pragma unroll
        for (int j = 0; j < 16; j++) { ulonglong2 t = bp[j]; A[2*j] = t.x; A[2*j+1] = t.y; }
    } else {
#pragma unroll
        for (int j = 0; j < 32; j++) A[j] = 0ull;
        float4 z = make_float4(0.f, 0.f, 0.f, 0.f);
        float4* ag = (float4*)(g_agg + (size_t)n * 32);
#pragma unroll
        for (int i = 0; i < 8; i++) ag[i] = z;
    }
    const float* wS = s_w0 + (half ? 32 : 0) * 64;
    const float* wD = s_w0 + (half ? 96 : 64) * 64;
    const float4* xs = (const float4*)(h_s + (size_t)n * 32);
    const float4* xd = (const float4*)(h_d + (size_t)n * 32);
#pragma unroll 1
    for (int i = 0; i < 8; i++) {
        float4 a = xs[i]; const float* w = wS + 4 * i * 64;
        rank1_64(a.x, w, A); rank1_64(a.y, w + 64, A);
        rank1_64(a.z, w + 128, A); rank1_64(a.w, w + 192, A);
    }
#pragma unroll 1
    for (int i = 0; i < 8; i++) {
        float4 a = xd[i]; const float* w = wD + 4 * i * 64;
        rank1_64(a.x, w, A); rank1_64(a.y, w + 64, A);
        rank1_64(a.z, w + 128, A); rank1_64(a.w, w + 192, A);
    }
    ulonglong2* o = (ulonglong2*)((half ? g_Q : g_P) + (size_t)n * 64);
#pragma unroll
    for (int j = 0; j < 16; j++) { ulonglong2 t; t.x = A[2*j]; t.y = A[2*j+1]; o[j] = t; }
}

// ---------------- edge kernel: tf32 MMA MLP ----------------
// smem: [0, 65536) weight frags (4096 ulonglong2), [65536, 65920) biases,
//       [65920, ...) per-warp h staging: 12 * 16*STR u64
#define SMEM_BYTES (65536 + 384 + ET / 32 * 16 * STR * 8)

__global__ void __launch_bounds__(ET, 1)
edge_kernel(const float* __restrict__ h_d, const float* __restrict__ ef,
            const int* __restrict__ si, const int* __restrict__ ri,
            const float* __restrict__ b1, const float* __restrict__ b2) {
    extern __shared__ ulonglong2 smem_v2[];
    ulonglong2* sB0 = smem_v2;          // 1024 entries
    ulonglong2* sB1 = smem_v2 + 1024;   // 2048
    ulonglong2* sB2 = smem_v2 + 3072;   // 1024
    float* s_b1 = (float*)(smem_v2 + 4096);
    float* s_b2 = s_b1 + 64;
    u64* s_h = (u64*)(s_b2 + 32);

    const int tid = threadIdx.x, wid = tid >> 5, lane = tid & 31;
    for (int i = tid; i < 4096; i += ET) smem_v2[i] = g_Ball[i];
    if (tid < 64) s_b1[tid] = b1[tid];
    if (tid < 32) s_b2[tid] = b2[tid];
    __syncthreads();

    u64* myh = s_h + wid * (16 * STR);
    const int r0 = lane >> 2, q = lane & 3;
    const int col2 = 2 * q;

#pragma unroll 1
    for (int base = blockIdx.x * 192 + wid * 16; base < NE; base += NBLK * 192) {
        int e0 = base + r0, e1 = e0 + 8;
        bool v0 = e0 < NE, v1 = e1 < NE;
        int e0c = v0 ? e0 : NE - 1;
        int e1c = v1 ? e1 : NE - 1;
        int s0 = si[e0c], rc0 = ri[e0c];
        int s1 = si[e1c], rc1 = ri[e1c];

        // ===== layer 0: C init from P[s]+Q[r], then ef @ W0e (K=32) =====
        float C[8][4];
        {
            const float* P0 = g_P + (size_t)s0 * 64;
            const float* Q0 = g_Q + (size_t)rc0 * 64;
            const float* P1 = g_P + (size_t)s1 * 64;
            const float* Q1 = g_Q + (size_t)rc1 * 64;
#pragma unroll
            for (int nt = 0; nt < 8; nt++) {
                int c = nt * 8 + col2;
                float2 p = *(const float2*)(P0 + c);
                float2 qv = *(const float2*)(Q0 + c);
                C[nt][0] = p.x + qv.x; C[nt][1] = p.y + qv.y;
                p = *(const float2*)(P1 + c);
                qv = *(const float2*)(Q1 + c);
                C[nt][2] = p.x + qv.x; C[nt][3] = p.y + qv.y;
            }
        }
#pragma unroll
        for (int kc = 0; kc < 4; kc++) {
            int c0 = kc * 8 + q;
            u32 ah[4], al[4];
            split_tf32(ef[(size_t)e0c * 32 + c0],     ah[0], al[0]);
            split_tf32(ef[(size_t)e1c * 32 + c0],     ah[1], al[1]);
            split_tf32(ef[(size_t)e0c * 32 + c0 + 4], ah[2], al[2]);
            split_tf32(ef[(size_t)e1c * 32 + c0 + 4], ah[3], al[3]);
            gemm_step<8>(C, ah, al, sB0, kc, 4, lane);
        }
        // relu -> stage h0 (hi|lo packed)
#pragma unroll
        for (int nt = 0; nt < 8; nt++) {
            int cc = nt * 8 + col2;
            myh[r0 * STR + cc]           = relu_split_pack(C[nt][0]);
            myh[r0 * STR + cc + 1]       = relu_split_pack(C[nt][1]);
            myh[(r0 + 8) * STR + cc]     = relu_split_pack(C[nt][2]);
            myh[(r0 + 8) * STR + cc + 1] = relu_split_pack(C[nt][3]);
        }
        __syncwarp();

        // ===== layer 1: h0 @ W1 (K=64) =====
#pragma unroll
        for (int nt = 0; nt < 8; nt++) {
            float bb0 = s_b1[nt * 8 + col2], bb1 = s_b1[nt * 8 + col2 + 1];
            C[nt][0] = bb0; C[nt][1] = bb1; C[nt][2] = bb0; C[nt][3] = bb1;
        }
#pragma unroll 2
        for (int kc = 0; kc < 8; kc++) {
            u32 ah[4], al[4];
            u64 t0 = myh[r0 * STR + kc * 8 + q];
            u64 t1 = myh[(r0 + 8) * STR + kc * 8 + q];
            u64 t2 = myh[r0 * STR + kc * 8 + q + 4];
            u64 t3 = myh[(r0 + 8) * STR + kc * 8 + q + 4];
            ah[0] = (u32)t0; al[0] = (u32)(t0 >> 32);
            ah[1] = (u32)t1; al[1] = (u32)(t1 >> 32);
            ah[2] = (u32)t2; al[2] = (u32)(t2 >> 32);
            ah[3] = (u32)t3; al[3] = (u32)(t3 >> 32);
            gemm_step<8>(C, ah, al, sB1, kc, 8, lane);
        }
        __syncwarp();
        // relu -> stage h1
#pragma unroll
        for (int nt = 0; nt < 8; nt++) {
            int cc = nt * 8 + col2;
            myh[r0 * STR + cc]           = relu_split_pack(C[nt][0]);
            myh[r0 * STR + cc + 1]       = relu_split_pack(C[nt][1]);
            myh[(r0 + 8) * STR + cc]     = relu_split_pack(C[nt][2]);
            myh[(r0 + 8) * STR + cc + 1] = relu_split_pack(C[nt][3]);
        }
        __syncwarp();

        // ===== layer 2: h1 @ W2 (K=64, N=32) =====
        float C2[4][4];
#pragma unroll
        for (int nt = 0; nt < 4; nt++) {
            float bb0 = s_b2[nt * 8 + col2], bb1 = s_b2[nt * 8 + col2 + 1];
            C2[nt][0] = bb0; C2[nt][1] = bb1; C2[nt][2] = bb0; C2[nt][3] = bb1;
        }
#pragma unroll 2
        for (int kc = 0; kc < 8; kc++) {
            u32 ah[4], al[4];
            u64 t0 = myh[r0 * STR + kc * 8 + q];
            u64 t1 = myh[(r0 + 8) * STR + kc * 8 + q];
            u64 t2 = myh[r0 * STR + kc * 8 + q + 4];
            u64 t3 = myh[(r0 + 8) * STR + kc * 8 + q + 4];
            ah[0] = (u32)t0; al[0] = (u32)(t0 >> 32);
            ah[1] = (u32)t1; al[1] = (u32)(t1 >> 32);
            ah[2] = (u32)t2; al[2] = (u32)(t2 >> 32);
            ah[3] = (u32)t3; al[3] = (u32)(t3 >> 32);
            gemm_step<4>(C2, ah, al, sB2, kc, 8, lane);
        }
        __syncwarp();   // protect myh before next-iteration overwrite

        // ===== epilogue: relu(psi) * (h_dj - h_di), vector scatter-add =====
#pragma unroll
        for (int nt = 0; nt < 4; nt++) {
            int cc = nt * 8 + col2;
            if (v0) {
                float2 dj = *(const float2*)(h_d + (size_t)rc0 * 32 + cc);
                float2 di = *(const float2*)(h_d + (size_t)s0 * 32 + cc);
                red2(g_agg + (size_t)rc0 * 32 + cc,
                     fmaxf(C2[nt][0], 0.f) * (dj.x - di.x),
                     fmaxf(C2[nt][1], 0.f) * (dj.y - di.y));
            }
            if (v1) {
                float2 dj = *(const float2*)(h_d + (size_t)rc1 * 32 + cc);
                float2 di = *(const float2*)(h_d + (size_t)s1 * 32 + cc);
                red2(g_agg + (size_t)rc1 * 32 + cc,
                     fmaxf(C2[nt][2], 0.f) * (dj.x - di.x),
                     fmaxf(C2[nt][3], 0.f) * (dj.y - di.y));
            }
        }
    }
}

// out[n] = h_d_prev[n] + agg[n] @ W   (thread per node, FFMA2 rank-1)
__global__ void __launch_bounds__(256)
final_kernel(const float* __restrict__ h_d, const float* __restrict__ W,
             float* __restrict__ out) {
    __shared__ float sW[1024];
    int tid = threadIdx.x;
    {
        float4* d4 = (float4*)sW;
        const float4* s4 = (const float4*)W;
        for (int i = tid; i < 256; i += 256) d4[i] = s4[i];
    }
    __syncthreads();
    int n = blockIdx.x * 256 + tid;
    if (n >= NN) return;

    u64 acc[16];
    {
        const ulonglong2* hp = (const ulonglong2*)(h_d + (size_t)n * 32);
#pragma unroll
        for (int j = 0; j < 8; j++) {
            ulonglong2 t = hp[j];
            acc[2 * j] = t.x; acc[2 * j + 1] = t.y;
        }
    }
    const float4* ap = (const float4*)(g_agg + (size_t)n * 32);
#pragma unroll
    for (int i = 0; i < 8; i++) {
        float4 a = ap[i];
        rank1_32(a.x, sW + (4 * i) * 32,     acc);
        rank1_32(a.y, sW + (4 * i + 1) * 32, acc);
        rank1_32(a.z, sW + (4 * i + 2) * 32, acc);
        rank1_32(a.w, sW + (4 * i + 3) * 32, acc);
    }
    ulonglong2* op = (ulonglong2*)(out + (size_t)n * 32);
#pragma unroll
    for (int j = 0; j < 8; j++) {
        ulonglong2 t; t.x = acc[2 * j]; t.y = acc[2 * j + 1];
        op[j] = t;
    }
}

extern "C" void kernel_launch(void* const* d_in, const int* in_sizes, int n_in,
                              void* d_out, int out_size) {
    const float* h_d = (const float*)d_in[0];
    const float* h_s = (const float*)d_in[1];
    const float* ef  = (const float*)d_in[2];
    const int*   si  = (const int*)d_in[3];
    const int*   ri  = (const int*)d_in[4];
    const float* w0  = (const float*)d_in[5];
    const float* b0  = (const float*)d_in[6];
    const float* w1  = (const float*)d_in[7];
    const float* b1  = (const float*)d_in[8];
    const float* w2  = (const float*)d_in[9];
    const float* b2  = (const float*)d_in[10];
    const float* W   = (const float*)d_in[11];
    float* out = (float*)d_out;

    cudaFuncSetAttribute(edge_kernel, cudaFuncAttributeMaxDynamicSharedMemorySize,
                         SMEM_BYTES);

    setup_kernel<<<16, 256>>>(w0, w1, w2);
    precompute_kernel<<<(NN + 127) / 128, 256>>>(h_s, h_d, w0, b0);
    edge_kernel<<<NBLK, ET, SMEM_BYTES>>>(h_d, ef, si, ri, b1, b2);
    final_kernel<<<(NN + 255) / 256, 256>>>(h_d, W, out);
}

// round 5
// speedup vs baseline: 1.9840x; 1.1380x over previous
#include <cuda_runtime.h>
#include <cstdint>

#define NN 100000
#define NE 800000
#define NBLK 148
#define ET 384          // edge kernel threads (12 warps)

typedef unsigned long long u64;
typedef unsigned int u32;

// scratch (allocation-free rule: __device__ globals)
__device__ float g_agg[NN * 32];
__device__ float g_P[NN * 64];          // physical fragment order
__device__ float g_Q[NN * 64];
__device__ ulonglong2 g_Ball[4096];     // edge weight frags (B0|B1|B2), hi|lo packed
__device__ ulonglong2 g_BP[4096];       // precompute weight frags (P|Q halves)
__device__ float g_b0p[64], g_b1p[64], g_b2c[32];

// ---------------- packed fp32x2 helpers (final kernel) ----------------
__device__ __forceinline__ u64 pack2(float x) {
    u64 r; asm("mov.b64 %0, {%1, %1};" : "=l"(r) : "f"(x)); return r;
}
__device__ __forceinline__ void ffma2(u64& d, u64 a, u64 b) {
    asm("fma.rn.f32x2 %0, %1, %2, %0;" : "+l"(d) : "l"(a), "l"(b));
}
__device__ __forceinline__ void rank1_32(float xf, const float* wrow, u64* a0) {
    u64 xa = pack2(xf);
    const ulonglong2* wr = (const ulonglong2*)wrow;
#pragma unroll
    for (int j = 0; j < 8; j++) {
        ulonglong2 w = wr[j];
        ffma2(a0[2 * j],     xa, w.x);
        ffma2(a0[2 * j + 1], xa, w.y);
    }
}

// ---------------- tf32 helpers ----------------
__device__ __forceinline__ void split_tf32(float x, u32& hi, u32& lo) {
    asm("cvt.rna.tf32.f32 %0, %1;" : "=r"(hi) : "f"(x));
    float r = x - __uint_as_float(hi);
    asm("cvt.rna.tf32.f32 %0, %1;" : "=r"(lo) : "f"(r));
}
__device__ __forceinline__ void mma_(float c[4], const u32 a[4], u32 b0, u32 b1) {
    asm volatile(
        "mma.sync.aligned.m16n8k8.row.col.f32.tf32.tf32.f32 "
        "{%0,%1,%2,%3}, {%4,%5,%6,%7}, {%8,%9}, {%0,%1,%2,%3};"
        : "+f"(c[0]), "+f"(c[1]), "+f"(c[2]), "+f"(c[3])
        : "r"(a[0]), "r"(a[1]), "r"(a[2]), "r"(a[3]), "r"(b0), "r"(b1));
}
// one K-chunk of compensated GEMM across NTC n-tiles
template <int NTC>
__device__ __forceinline__ void gemm_step(float C[][4], const u32 ah[4], const u32 al[4],
                                          const ulonglong2* sB, int kc, int Kc, int lane) {
    u32 bh[NTC][2], bl[NTC][2];
#pragma unroll
    for (int nt = 0; nt < NTC; nt++) {
        ulonglong2 t = sB[(nt * Kc + kc) * 32 + lane];
        bh[nt][0] = (u32)t.x; bl[nt][0] = (u32)(t.x >> 32);
        bh[nt][1] = (u32)t.y; bl[nt][1] = (u32)(t.y >> 32);
    }
#pragma unroll
    for (int nt = 0; nt < NTC; nt++) mma_(C[nt], ah, bh[nt][0], bh[nt][1]);
#pragma unroll
    for (int nt = 0; nt < NTC; nt++) mma_(C[nt], ah, bl[nt][0], bl[nt][1]);
#pragma unroll
    for (int nt = 0; nt < NTC; nt++) mma_(C[nt], al, bh[nt][0], bh[nt][1]);
}
// relu + split C-fragment into next layer's A-fragment (layout identity via perm)
__device__ __forceinline__ void build_a(const float c[4], u32 ah[4], u32 al[4]) {
    split_tf32(fmaxf(c[0], 0.f), ah[0], al[0]);
    split_tf32(fmaxf(c[2], 0.f), ah[1], al[1]);
    split_tf32(fmaxf(c[1], 0.f), ah[2], al[2]);
    split_tf32(fmaxf(c[3], 0.f), ah[3], al[3]);
}
__device__ __forceinline__ void red2(float* p, float x, float y) {
    asm volatile("red.global.add.v2.f32 [%0], {%1,%2};" :: "l"(p), "f"(x), "f"(y) : "memory");
}

// ---------------- setup: fragment-ordered (hi|lo) weights, N-col permuted ----------------
__global__ void setup_kernel(const float* __restrict__ w0, const float* __restrict__ w1,
                             const float* __restrict__ w2, const float* __restrict__ b0,
                             const float* __restrict__ b1, const float* __restrict__ b2) {
    int i = blockIdx.x * 256 + threadIdx.x;
    const int prm[8] = {0, 4, 1, 5, 2, 6, 3, 7};
    if (i < 4096) {
        // edge frags: fe<32: W0e 8nt x 4kc (n perm); [32,96): W1 8x8 (n perm); [96,128): W2 4x8 (natural)
        int lane = i & 31, fe = i >> 5;
        int npos = lane >> 2, kq = lane & 3;
        const float* W; int nidx, k0, stride;
        if (fe < 32) {
            int nt = fe >> 2, kc = fe & 3;
            nidx = nt * 8 + prm[npos]; k0 = kc * 8 + kq; W = w0 + 128 * 64; stride = 64;
        } else if (fe < 96) {
            int f = fe - 32, nt = f >> 3, kc = f & 7;
            nidx = nt * 8 + prm[npos]; k0 = kc * 8 + kq; W = w1; stride = 64;
        } else {
            int f = fe - 96, nt = f >> 3, kc = f & 7;
            nidx = nt * 8 + npos; k0 = kc * 8 + kq; W = w2; stride = 32;
        }
        float v0 = W[(size_t)k0 * stride + nidx];
        float v1 = W[(size_t)(k0 + 4) * stride + nidx];
        u32 h0, l0, h1, l1;
        split_tf32(v0, h0, l0); split_tf32(v1, h1, l1);
        ulonglong2 t;
        t.x = (u64)h0 | ((u64)l0 << 32);
        t.y = (u64)h1 | ((u64)l1 << 32);
        g_Ball[i] = t;
    } else if (i < 8192) {
        // precompute frags: 16 nt (0..7 P, 8..15 Q) x 8 kc; X = [h_s | h_d]
        int j = i - 4096, lane = j & 31, f = j >> 5;
        int nt = f >> 3, kc = f & 7;
        int npos = lane >> 2, kq = lane & 3;
        int blk = nt & 7; bool isQ = nt >= 8;
        int nidx = blk * 8 + prm[npos];
        int k0 = kc * 8 + kq;
        int r0 = (k0 < 32) ? (isQ ? 32 + k0 : k0) : (isQ ? k0 + 64 : k0 + 32);
        int k1 = k0 + 4;
        int r1 = (k1 < 32) ? (isQ ? 32 + k1 : k1) : (isQ ? k1 + 64 : k1 + 32);
        float v0 = w0[(size_t)r0 * 64 + nidx];
        float v1 = w0[(size_t)r1 * 64 + nidx];
        u32 h0, l0, h1, l1;
        split_tf32(v0, h0, l0); split_tf32(v1, h1, l1);
        ulonglong2 t;
        t.x = (u64)h0 | ((u64)l0 << 32);
        t.y = (u64)h1 | ((u64)l1 << 32);
        g_BP[j] = t;
    } else if (i < 8192 + 160) {
        int t = i - 8192;
        if (t < 64)       g_b0p[t] = b0[(t & ~7) + prm[t & 7]];
        else if (t < 128) { int p = t - 64; g_b1p[p] = b1[(p & ~7) + prm[p & 7]]; }
        else              g_b2c[t - 128] = b2[t - 128];
    }
}

// ---------------- precompute: P|Q = [h_s|h_d] @ W' via tf32 MMA; zeros g_agg ----------------
__global__ void __launch_bounds__(256, 1)
pre_kernel(const float* __restrict__ h_s, const float* __restrict__ h_d) {
    extern __shared__ ulonglong2 smem_v2[];
    ulonglong2* sBP = smem_v2;                 // 4096 entries
    float* s_b0p = (float*)(smem_v2 + 4096);   // 64
    const int tid = threadIdx.x, wid = tid >> 5, lane = tid & 31;
    const int g = lane >> 2, q = lane & 3;
    for (int i = tid; i < 4096; i += 256) sBP[i] = g_BP[i];
    if (tid < 64) s_b0p[tid] = g_b0p[tid];
    __syncthreads();

    int n0 = (blockIdx.x * 8 + wid) * 16;
    if (n0 >= NN) return;   // after syncthreads; no later block syncs

    float C[16][4];
#pragma unroll
    for (int nt = 0; nt < 8; nt++) {
        C[nt][0] = 0.f; C[nt][1] = 0.f; C[nt][2] = 0.f; C[nt][3] = 0.f;
        float b0v = s_b0p[nt * 8 + 2 * q], b1v = s_b0p[nt * 8 + 2 * q + 1];
        C[8 + nt][0] = b0v; C[8 + nt][1] = b1v; C[8 + nt][2] = b0v; C[8 + nt][3] = b1v;
    }
#pragma unroll
    for (int kc = 0; kc < 8; kc++) {
        const float* src = (kc < 4) ? h_s : h_d;
        int off = (kc & 3) * 8;
        u32 ah[4], al[4];
        split_tf32(src[(size_t)(n0 + g) * 32 + off + q],         ah[0], al[0]);
        split_tf32(src[(size_t)(n0 + g + 8) * 32 + off + q],     ah[1], al[1]);
        split_tf32(src[(size_t)(n0 + g) * 32 + off + q + 4],     ah[2], al[2]);
        split_tf32(src[(size_t)(n0 + g + 8) * 32 + off + q + 4], ah[3], al[3]);
        gemm_step<8>(C,     ah, al, sBP,             kc, 8, lane);   // P half
        gemm_step<8>(C + 8, ah, al, sBP + 64 * 32,   kc, 8, lane);   // Q half
    }
    // store physical fragment order
#pragma unroll
    for (int nt = 0; nt < 8; nt++) {
        int cc = nt * 8 + 2 * q;
        *(float2*)(g_P + (size_t)(n0 + g) * 64 + cc)     = make_float2(C[nt][0], C[nt][1]);
        *(float2*)(g_P + (size_t)(n0 + g + 8) * 64 + cc) = make_float2(C[nt][2], C[nt][3]);
        *(float2*)(g_Q + (size_t)(n0 + g) * 64 + cc)     = make_float2(C[8+nt][0], C[8+nt][1]);
        *(float2*)(g_Q + (size_t)(n0 + g + 8) * 64 + cc) = make_float2(C[8+nt][2], C[8+nt][3]);
    }
    // zero g_agg rows n0..n0+15
    float4 z = make_float4(0.f, 0.f, 0.f, 0.f);
    float4* ag = (float4*)(g_agg + (size_t)n0 * 32);
#pragma unroll
    for (int i = 0; i < 4; i++) ag[lane + 32 * i] = z;
}

// ---------------- edge kernel: tf32 MMA MLP, zero staging ----------------
#define SMEM_BYTES (65536 + 96 * 4)

__global__ void __launch_bounds__(ET, 1)
edge_kernel(const float* __restrict__ h_d, const float* __restrict__ ef,
            const int* __restrict__ si, const int* __restrict__ ri) {
    extern __shared__ ulonglong2 smem_v2[];
    ulonglong2* sB0 = smem_v2;          // 1024
    ulonglong2* sB1 = smem_v2 + 1024;   // 2048
    ulonglong2* sB2 = smem_v2 + 3072;   // 1024
    float* s_b1p = (float*)(smem_v2 + 4096);
    float* s_b2  = s_b1p + 64;

    const int tid = threadIdx.x, wid = tid >> 5, lane = tid & 31;
    for (int i = tid; i < 4096; i += ET) smem_v2[i] = g_Ball[i];
    if (tid < 64) s_b1p[tid] = g_b1p[tid];
    if (tid < 32) s_b2[tid] = g_b2c[tid];
    __syncthreads();

    const int g = lane >> 2, q = lane & 3;
    const int col2 = 2 * q;

#pragma unroll 1
    for (int base = blockIdx.x * 192 + wid * 16; base < NE; base += NBLK * 192) {
        int e0 = base + g, e1 = e0 + 8;
        bool v0 = e0 < NE, v1 = e1 < NE;
        int e0c = v0 ? e0 : NE - 1;
        int e1c = v1 ? e1 : NE - 1;
        int s0 = si[e0c], rc0 = ri[e0c];
        int s1 = si[e1c], rc1 = ri[e1c];

        // ===== layer 0: C init from P[s]+Q[r] (physical), then ef @ W0e =====
        float C[8][4];
        {
            const float* P0 = g_P + (size_t)s0 * 64;
            const float* Q0 = g_Q + (size_t)rc0 * 64;
            const float* P1 = g_P + (size_t)s1 * 64;
            const float* Q1 = g_Q + (size_t)rc1 * 64;
#pragma unroll
            for (int nt = 0; nt < 8; nt++) {
                int c = nt * 8 + col2;
                float2 p = *(const float2*)(P0 + c);
                float2 qv = *(const float2*)(Q0 + c);
                C[nt][0] = p.x + qv.x; C[nt][1] = p.y + qv.y;
                p = *(const float2*)(P1 + c);
                qv = *(const float2*)(Q1 + c);
                C[nt][2] = p.x + qv.x; C[nt][3] = p.y + qv.y;
            }
        }
#pragma unroll
        for (int kc = 0; kc < 4; kc++) {
            int c0 = kc * 8 + q;
            u32 ah[4], al[4];
            split_tf32(ef[(size_t)e0c * 32 + c0],     ah[0], al[0]);
            split_tf32(ef[(size_t)e1c * 32 + c0],     ah[1], al[1]);
            split_tf32(ef[(size_t)e0c * 32 + c0 + 4], ah[2], al[2]);
            split_tf32(ef[(size_t)e1c * 32 + c0 + 4], ah[3], al[3]);
            gemm_step<8>(C, ah, al, sB0, kc, 4, lane);
        }

        // ===== layer 1: A built directly from C (relu+split, layout identity) =====
        float C1[8][4];
#pragma unroll
        for (int nt = 0; nt < 8; nt++) {
            float bb0 = s_b1p[nt * 8 + col2], bb1 = s_b1p[nt * 8 + col2 + 1];
            C1[nt][0] = bb0; C1[nt][1] = bb1; C1[nt][2] = bb0; C1[nt][3] = bb1;
        }
#pragma unroll 2
        for (int kc = 0; kc < 8; kc++) {
            u32 ah[4], al[4];
            build_a(C[kc], ah, al);
            gemm_step<8>(C1, ah, al, sB1, kc, 8, lane);
        }

        // ===== layer 2 =====
        float C2[4][4];
#pragma unroll
        for (int nt = 0; nt < 4; nt++) {
            float bb0 = s_b2[nt * 8 + col2], bb1 = s_b2[nt * 8 + col2 + 1];
            C2[nt][0] = bb0; C2[nt][1] = bb1; C2[nt][2] = bb0; C2[nt][3] = bb1;
        }
#pragma unroll 2
        for (int kc = 0; kc < 8; kc++) {
            u32 ah[4], al[4];
            build_a(C1[kc], ah, al);
            gemm_step<4>(C2, ah, al, sB2, kc, 8, lane);
        }

        // ===== epilogue: relu(psi) * (h_dj - h_di), vector scatter-add =====
#pragma unroll
        for (int nt = 0; nt < 4; nt++) {
            int cc = nt * 8 + col2;
            if (v0) {
                float2 dj = *(const float2*)(h_d + (size_t)rc0 * 32 + cc);
                float2 di = *(const float2*)(h_d + (size_t)s0 * 32 + cc);
                red2(g_agg + (size_t)rc0 * 32 + cc,
                     fmaxf(C2[nt][0], 0.f) * (dj.x - di.x),
                     fmaxf(C2[nt][1], 0.f) * (dj.y - di.y));
            }
            if (v1) {
                float2 dj = *(const float2*)(h_d + (size_t)rc1 * 32 + cc);
                float2 di = *(const float2*)(h_d + (size_t)s1 * 32 + cc);
                red2(g_agg + (size_t)rc1 * 32 + cc,
                     fmaxf(C2[nt][2], 0.f) * (dj.x - di.x),
                     fmaxf(C2[nt][3], 0.f) * (dj.y - di.y));
            }
        }
    }
}

// out[n] = h_d_prev[n] + agg[n] @ W   (thread per node, FFMA2 rank-1)
__global__ void __launch_bounds__(256)
final_kernel(const float* __restrict__ h_d, const float* __restrict__ W,
             float* __restrict__ out) {
    __shared__ float sW[1024];
    int tid = threadIdx.x;
    {
        float4* d4 = (float4*)sW;
        const float4* s4 = (const float4*)W;
        for (int i = tid; i < 256; i += 256) d4[i] = s4[i];
    }
    __syncthreads();
    int n = blockIdx.x * 256 + tid;
    if (n >= NN) return;

    u64 acc[16];
    {
        const ulonglong2* hp = (const ulonglong2*)(h_d + (size_t)n * 32);
#pragma unroll
        for (int j = 0; j < 8; j++) {
            ulonglong2 t = hp[j];
            acc[2 * j] = t.x; acc[2 * j + 1] = t.y;
        }
    }
    const float4* ap = (const float4*)(g_agg + (size_t)n * 32);
#pragma unroll
    for (int i = 0; i < 8; i++) {
        float4 a = ap[i];
        rank1_32(a.x, sW + (4 * i) * 32,     acc);
        rank1_32(a.y, sW + (4 * i + 1) * 32, acc);
        rank1_32(a.z, sW + (4 * i + 2) * 32, acc);
        rank1_32(a.w, sW + (4 * i + 3) * 32, acc);
    }
    ulonglong2* op = (ulonglong2*)(out + (size_t)n * 32);
#pragma unroll
    for (int j = 0; j < 8; j++) {
        ulonglong2 t; t.x = acc[2 * j]; t.y = acc[2 * j + 1];
        op[j] = t;
    }
}

extern "C" void kernel_launch(void* const* d_in, const int* in_sizes, int n_in,
                              void* d_out, int out_size) {
    const float* h_d = (const float*)d_in[0];
    const float* h_s = (const float*)d_in[1];
    const float* ef  = (const float*)d_in[2];
    const int*   si  = (const int*)d_in[3];
    const int*   ri  = (const int*)d_in[4];
    const float* w0  = (const float*)d_in[5];
    const float* b0  = (const float*)d_in[6];
    const float* w1  = (const float*)d_in[7];
    const float* b1  = (const float*)d_in[8];
    const float* w2  = (const float*)d_in[9];
    const float* b2  = (const float*)d_in[10];
    const float* W   = (const float*)d_in[11];
    float* out = (float*)d_out;

    cudaFuncSetAttribute(edge_kernel, cudaFuncAttributeMaxDynamicSharedMemorySize,
                         SMEM_BYTES);
    cudaFuncSetAttribute(pre_kernel, cudaFuncAttributeMaxDynamicSharedMemorySize,
                         65536 + 64 * 4);

    setup_kernel<<<33, 256>>>(w0, w1, w2, b0, b1, b2);
    pre_kernel<<<782, 256, 65536 + 64 * 4>>>(h_s, h_d);
    edge_kernel<<<NBLK, ET, SMEM_BYTES>>>(h_d, ef, si, ri);
    final_kernel<<<(NN + 255) / 256, 256>>>(h_d, W, out);
}

// round 6
// speedup vs baseline: 3.1616x; 1.5936x over previous
#include <cuda_runtime.h>
#include <cstdint>

#define NN 100000
#define NE 800000
#define NBLK 148
#define ET 384          // edge kernel threads (12 warps)

typedef unsigned long long u64;
typedef unsigned int u32;

// scratch (allocation-free rule: __device__ globals)
__device__ float g_agg[NN * 32];
__device__ float g_P[NN * 64];          // fragment-major: [n][q*16 + nt*2 + c]
__device__ float g_Q[NN * 64];
__device__ ulonglong2 g_Ball[2048];     // edge weight frags (B0|B1|B2), bf16 hi|lo
__device__ ulonglong2 g_BP[2048];       // precompute weight frags (P|Q halves)

// ---------------- packed fp32x2 helpers (final kernel) ----------------
__device__ __forceinline__ u64 pack2(float x) {
    u64 r; asm("mov.b64 %0, {%1, %1};" : "=l"(r) : "f"(x)); return r;
}
__device__ __forceinline__ void ffma2(u64& d, u64 a, u64 b) {
    asm("fma.rn.f32x2 %0, %1, %2, %0;" : "+l"(d) : "l"(a), "l"(b));
}
__device__ __forceinline__ void rank1_32(float xf, const float* wrow, u64* a0) {
    u64 xa = pack2(xf);
    const ulonglong2* wr = (const ulonglong2*)wrow;
#pragma unroll
    for (int j = 0; j < 8; j++) {
        ulonglong2 w = wr[j];
        ffma2(a0[2 * j],     xa, w.x);
        ffma2(a0[2 * j + 1], xa, w.y);
    }
}

// ---------------- bf16 emulation helpers ----------------
// pack two f32 -> bf16x2: low half = x0, high half = x1
__device__ __forceinline__ u32 bf2pack(float x0, float x1) {
    u32 r;
    asm("cvt.rn.bf16x2.f32 %0, %1, %2;" : "=r"(r) : "f"(x1), "f"(x0));
    return r;
}
// split (x0,x1) into bf16x2 hi + bf16x2 lo residual
__device__ __forceinline__ void split_bf2(float x0, float x1, u32& h, u32& l) {
    h = bf2pack(x0, x1);
    float r0 = x0 - __uint_as_float(h << 16);
    float r1 = x1 - __uint_as_float(h & 0xFFFF0000u);
    l = bf2pack(r0, r1);
}
__device__ __forceinline__ void mma_bf(float c[4], const u32 a[4], u32 b0, u32 b1) {
    asm volatile(
        "mma.sync.aligned.m16n8k16.row.col.f32.bf16.bf16.f32 "
        "{%0,%1,%2,%3}, {%4,%5,%6,%7}, {%8,%9}, {%0,%1,%2,%3};"
        : "+f"(c[0]), "+f"(c[1]), "+f"(c[2]), "+f"(c[3])
        : "r"(a[0]), "r"(a[1]), "r"(a[2]), "r"(a[3]), "r"(b0), "r"(b1));
}
// one K=16 chunk of compensated GEMM across NTC n-tiles
template <int NTC>
__device__ __forceinline__ void gemm_step(float C[][4], const u32 ah[4], const u32 al[4],
                                          const ulonglong2* sB, int kc, int Kc, int lane) {
    u32 bh[NTC][2], bl[NTC][2];
#pragma unroll
    for (int nt = 0; nt < NTC; nt++) {
        ulonglong2 t = sB[(nt * Kc + kc) * 32 + lane];
        bh[nt][0] = (u32)t.x; bl[nt][0] = (u32)(t.x >> 32);
        bh[nt][1] = (u32)t.y; bl[nt][1] = (u32)(t.y >> 32);
    }
#pragma unroll
    for (int nt = 0; nt < NTC; nt++) mma_bf(C[nt], ah, bh[nt][0], bh[nt][1]);
#pragma unroll
    for (int nt = 0; nt < NTC; nt++) mma_bf(C[nt], ah, bl[nt][0], bl[nt][1]);
#pragma unroll
    for (int nt = 0; nt < NTC; nt++) mma_bf(C[nt], al, bh[nt][0], bh[nt][1]);
}
// relu C-fragments of two adjacent n-tiles -> next layer's A fragment (identity layout)
__device__ __forceinline__ void build_a(const float cA[4], const float cB[4],
                                        u32 ah[4], u32 al[4]) {
    split_bf2(fmaxf(cA[0], 0.f), fmaxf(cA[1], 0.f), ah[0], al[0]);
    split_bf2(fmaxf(cA[2], 0.f), fmaxf(cA[3], 0.f), ah[1], al[1]);
    split_bf2(fmaxf(cB[0], 0.f), fmaxf(cB[1], 0.f), ah[2], al[2]);
    split_bf2(fmaxf(cB[2], 0.f), fmaxf(cB[3], 0.f), ah[3], al[3]);
}
__device__ __forceinline__ void red2(float* p, float x, float y) {
    asm volatile("red.global.add.v2.f32 [%0], {%1,%2};" :: "l"(p), "f"(x), "f"(y) : "memory");
}

// ---------------- setup: natural-order bf16 hi|lo weight fragments ----------------
// edge frags f<16: W0e (8nt x 2kc); [16,48): W1 (8x4); [48,64): W2 (4x4)
// pre frags (f-64): 16nt x 4kc over X=[h_s|h_d] rows of W0
__global__ void setup_kernel(const float* __restrict__ w0, const float* __restrict__ w1,
                             const float* __restrict__ w2) {
    int i = blockIdx.x * 256 + threadIdx.x;
    if (i >= 4096) return;
    int lane = i & 31, f = i >> 5;
    int g = lane >> 2, q = lane & 3;
    float v00, v01, v10, v11;
    if (f < 64) {
        const float* W; int nidx, k0, stride;
        if (f < 16)      { int nt = f >> 1,  kc = f & 1;  W = w0 + 128 * 64; stride = 64; nidx = nt * 8 + g; k0 = 16 * kc + 2 * q; }
        else if (f < 48) { int ff = f - 16; int nt = ff >> 2, kc = ff & 3; W = w1; stride = 64; nidx = nt * 8 + g; k0 = 16 * kc + 2 * q; }
        else             { int ff = f - 48; int nt = ff >> 2, kc = ff & 3; W = w2; stride = 32; nidx = nt * 8 + g; k0 = 16 * kc + 2 * q; }
        v00 = W[(size_t)k0 * stride + nidx];
        v01 = W[(size_t)(k0 + 1) * stride + nidx];
        v10 = W[(size_t)(k0 + 8) * stride + nidx];
        v11 = W[(size_t)(k0 + 9) * stride + nidx];
    } else {
        int ff = f - 64;
        int nt = ff >> 2, kc = ff & 3;
        int isq = (nt >= 8) ? 32 : 0;
        int nidx = (nt & 7) * 8 + g;
        int k0 = 16 * kc + 2 * q;
        int r00 = ((k0     < 32) ? k0     : k0 + 32) + isq;
        int r01 = ((k0 + 1 < 32) ? k0 + 1 : k0 + 33) + isq;
        int r10 = ((k0 + 8 < 32) ? k0 + 8 : k0 + 40) + isq;
        int r11 = ((k0 + 9 < 32) ? k0 + 9 : k0 + 41) + isq;
        v00 = w0[(size_t)r00 * 64 + nidx];
        v01 = w0[(size_t)r01 * 64 + nidx];
        v10 = w0[(size_t)r10 * 64 + nidx];
        v11 = w0[(size_t)r11 * 64 + nidx];
    }
    u32 h0, l0, h1, l1;
    split_bf2(v00, v01, h0, l0);
    split_bf2(v10, v11, h1, l1);
    ulonglong2 t;
    t.x = (u64)h0 | ((u64)l0 << 32);
    t.y = (u64)h1 | ((u64)l1 << 32);
    if (f < 64) g_Ball[i] = t; else g_BP[i - 2048] = t;
}

// ---------------- precompute: P|Q = [h_s|h_d] @ W' via bf16 MMA; zeros g_agg ----------------
__global__ void __launch_bounds__(256, 1)
pre_kernel(const float* __restrict__ h_s, const float* __restrict__ h_d,
           const float* __restrict__ b0) {
    extern __shared__ ulonglong2 smem_v2[];
    float* s_b0 = (float*)(smem_v2 + 2048);
    const int tid = threadIdx.x, wid = tid >> 5, lane = tid & 31;
    const int g = lane >> 2, q = lane & 3;
    for (int i = tid; i < 2048; i += 256) smem_v2[i] = g_BP[i];
    if (tid < 64) s_b0[tid] = b0[tid];
    __syncthreads();

    int n0 = (blockIdx.x * 8 + wid) * 16;
    if (n0 >= NN) return;   // NN % 16 == 0: tiles are all-in or all-out

    float C[16][4];
#pragma unroll
    for (int nt = 0; nt < 8; nt++) {
        C[nt][0] = 0.f; C[nt][1] = 0.f; C[nt][2] = 0.f; C[nt][3] = 0.f;
        float b0v = s_b0[nt * 8 + 2 * q], b1v = s_b0[nt * 8 + 2 * q + 1];
        C[8 + nt][0] = b0v; C[8 + nt][1] = b1v; C[8 + nt][2] = b0v; C[8 + nt][3] = b1v;
    }
#pragma unroll
    for (int kc = 0; kc < 4; kc++) {
        const float* src = (kc < 2) ? h_s : h_d;
        int off = (kc & 1) * 16 + 2 * q;
        float2 x0 = *(const float2*)(src + (size_t)(n0 + g) * 32 + off);
        float2 x1 = *(const float2*)(src + (size_t)(n0 + 8 + g) * 32 + off);
        float2 x2 = *(const float2*)(src + (size_t)(n0 + g) * 32 + off + 8);
        float2 x3 = *(const float2*)(src + (size_t)(n0 + 8 + g) * 32 + off + 8);
        u32 ah[4], al[4];
        split_bf2(x0.x, x0.y, ah[0], al[0]);
        split_bf2(x1.x, x1.y, ah[1], al[1]);
        split_bf2(x2.x, x2.y, ah[2], al[2]);
        split_bf2(x3.x, x3.y, ah[3], al[3]);
        gemm_step<8>(C,     ah, al, smem_v2,           kc, 4, lane);   // P
        gemm_step<8>(C + 8, ah, al, smem_v2 + 32 * 32, kc, 4, lane);   // Q
    }
    // store fragment-major: [n][q*16 + nt*2]
#pragma unroll
    for (int j = 0; j < 4; j++) {
        *(float4*)(g_P + (size_t)(n0 + g)     * 64 + q * 16 + 4 * j) =
            make_float4(C[2*j][0], C[2*j][1], C[2*j+1][0], C[2*j+1][1]);
        *(float4*)(g_P + (size_t)(n0 + 8 + g) * 64 + q * 16 + 4 * j) =
            make_float4(C[2*j][2], C[2*j][3], C[2*j+1][2], C[2*j+1][3]);
        *(float4*)(g_Q + (size_t)(n0 + g)     * 64 + q * 16 + 4 * j) =
            make_float4(C[8+2*j][0], C[8+2*j][1], C[8+2*j+1][0], C[8+2*j+1][1]);
        *(float4*)(g_Q + (size_t)(n0 + 8 + g) * 64 + q * 16 + 4 * j) =
            make_float4(C[8+2*j][2], C[8+2*j][3], C[8+2*j+1][2], C[8+2*j+1][3]);
    }
    // zero g_agg rows n0..n0+15
    float4 z = make_float4(0.f, 0.f, 0.f, 0.f);
    float4* ag = (float4*)(g_agg + (size_t)n0 * 32);
#pragma unroll
    for (int i = 0; i < 4; i++) ag[lane + 32 * i] = z;
}

// ---------------- edge kernel: bf16 MMA MLP, zero staging, no permutation ----------------
#define SMEM_BYTES (2048 * 16 + 96 * 4)

__global__ void __launch_bounds__(ET, 1)
edge_kernel(const float* __restrict__ h_d, const float* __restrict__ ef,
            const int* __restrict__ si, const int* __restrict__ ri,
            const float* __restrict__ b1, const float* __restrict__ b2) {
    extern __shared__ ulonglong2 smem_v2[];
    ulonglong2* sB0 = smem_v2;           // 16 frags
    ulonglong2* sB1 = smem_v2 + 512;     // 32 frags
    ulonglong2* sB2 = smem_v2 + 1536;    // 16 frags
    float* s_b1 = (float*)(smem_v2 + 2048);
    float* s_b2 = s_b1 + 64;

    const int tid = threadIdx.x, wid = tid >> 5, lane = tid & 31;
    for (int i = tid; i < 2048; i += ET) smem_v2[i] = g_Ball[i];
    if (tid < 64) s_b1[tid] = b1[tid];
    if (tid < 32) s_b2[tid] = b2[tid];
    __syncthreads();

    const int g = lane >> 2, q = lane & 3;
    const int col2 = 2 * q;

#pragma unroll 1
    for (int base = blockIdx.x * 192 + wid * 16; base < NE; base += NBLK * 192) {
        int e0 = base + g, e1 = base + 8 + g;
        bool v0 = e0 < NE, v1 = e1 < NE;
        int e0c = v0 ? e0 : NE - 1;
        int e1c = v1 ? e1 : NE - 1;
        int s0 = si[e0c], rc0 = ri[e0c];
        int s1 = si[e1c], rc1 = ri[e1c];

        // ===== layer 0: C init from P[s]+Q[r] (fragment-major float4 gathers) =====
        float C[8][4];
        {
            const float4* P0 = (const float4*)(g_P + (size_t)s0  * 64 + q * 16);
            const float4* Q0 = (const float4*)(g_Q + (size_t)rc0 * 64 + q * 16);
            const float4* P1 = (const float4*)(g_P + (size_t)s1  * 64 + q * 16);
            const float4* Q1 = (const float4*)(g_Q + (size_t)rc1 * 64 + q * 16);
#pragma unroll
            for (int j = 0; j < 4; j++) {
                float4 p = P0[j], qq = Q0[j];
                C[2*j][0]   = p.x + qq.x; C[2*j][1]   = p.y + qq.y;
                C[2*j+1][0] = p.z + qq.z; C[2*j+1][1] = p.w + qq.w;
                p = P1[j]; qq = Q1[j];
                C[2*j][2]   = p.x + qq.x; C[2*j][3]   = p.y + qq.y;
                C[2*j+1][2] = p.z + qq.z; C[2*j+1][3] = p.w + qq.w;
            }
        }
        // ===== layer 0: += ef @ W0e (K=32, 2 chunks) =====
#pragma unroll
        for (int kc = 0; kc < 2; kc++) {
            int off = 16 * kc + col2;
            float2 x0 = *(const float2*)(ef + (size_t)e0c * 32 + off);
            float2 x1 = *(const float2*)(ef + (size_t)e1c * 32 + off);
            float2 x2 = *(const float2*)(ef + (size_t)e0c * 32 + off + 8);
            float2 x3 = *(const float2*)(ef + (size_t)e1c * 32 + off + 8);
            u32 ah[4], al[4];
            split_bf2(x0.x, x0.y, ah[0], al[0]);
            split_bf2(x1.x, x1.y, ah[1], al[1]);
            split_bf2(x2.x, x2.y, ah[2], al[2]);
            split_bf2(x3.x, x3.y, ah[3], al[3]);
            gemm_step<8>(C, ah, al, sB0, kc, 2, lane);
        }

        // ===== layer 1 (K=64, 4 chunks; A chained from C) =====
        float C1[8][4];
#pragma unroll
        for (int nt = 0; nt < 8; nt++) {
            float bb0 = s_b1[nt * 8 + col2], bb1 = s_b1[nt * 8 + col2 + 1];
            C1[nt][0] = bb0; C1[nt][1] = bb1; C1[nt][2] = bb0; C1[nt][3] = bb1;
        }
#pragma unroll
        for (int kc = 0; kc < 4; kc++) {
            u32 ah[4], al[4];
            build_a(C[2 * kc], C[2 * kc + 1], ah, al);
            gemm_step<8>(C1, ah, al, sB1, kc, 4, lane);
        }

        // ===== layer 2 (K=64 -> N=32) =====
        float C2[4][4];
#pragma unroll
        for (int nt = 0; nt < 4; nt++) {
            float bb0 = s_b2[nt * 8 + col2], bb1 = s_b2[nt * 8 + col2 + 1];
            C2[nt][0] = bb0; C2[nt][1] = bb1; C2[nt][2] = bb0; C2[nt][3] = bb1;
        }
#pragma unroll
        for (int kc = 0; kc < 4; kc++) {
            u32 ah[4], al[4];
            build_a(C1[2 * kc], C1[2 * kc + 1], ah, al);
            gemm_step<4>(C2, ah, al, sB2, kc, 4, lane);
        }

        // ===== epilogue: relu(psi) * (h_dj - h_di), vector scatter-add =====
#pragma unroll
        for (int nt = 0; nt < 4; nt++) {
            int cc = nt * 8 + col2;
            if (v0) {
                float2 dj = *(const float2*)(h_d + (size_t)rc0 * 32 + cc);
                float2 di = *(const float2*)(h_d + (size_t)s0 * 32 + cc);
                red2(g_agg + (size_t)rc0 * 32 + cc,
                     fmaxf(C2[nt][0], 0.f) * (dj.x - di.x),
                     fmaxf(C2[nt][1], 0.f) * (dj.y - di.y));
            }
            if (v1) {
                float2 dj = *(const float2*)(h_d + (size_t)rc1 * 32 + cc);
                float2 di = *(const float2*)(h_d + (size_t)s1 * 32 + cc);
                red2(g_agg + (size_t)rc1 * 32 + cc,
                     fmaxf(C2[nt][2], 0.f) * (dj.x - di.x),
                     fmaxf(C2[nt][3], 0.f) * (dj.y - di.y));
            }
        }
    }
}

// out[n] = h_d_prev[n] + agg[n] @ W   (thread per node, FFMA2 rank-1)
__global__ void __launch_bounds__(256)
final_kernel(const float* __restrict__ h_d, const float* __restrict__ W,
             float* __restrict__ out) {
    __shared__ float sW[1024];
    int tid = threadIdx.x;
    {
        float4* d4 = (float4*)sW;
        const float4* s4 = (const float4*)W;
        for (int i = tid; i < 256; i += 256) d4[i] = s4[i];
    }
    __syncthreads();
    int n = blockIdx.x * 256 + tid;
    if (n >= NN) return;

    u64 acc[16];
    {
        const ulonglong2* hp = (const ulonglong2*)(h_d + (size_t)n * 32);
#pragma unroll
        for (int j = 0; j < 8; j++) {
            ulonglong2 t = hp[j];
            acc[2 * j] = t.x; acc[2 * j + 1] = t.y;
        }
    }
    const float4* ap = (const float4*)(g_agg + (size_t)n * 32);
#pragma unroll
    for (int i = 0; i < 8; i++) {
        float4 a = ap[i];
        rank1_32(a.x, sW + (4 * i) * 32,     acc);
        rank1_32(a.y, sW + (4 * i + 1) * 32, acc);
        rank1_32(a.z, sW + (4 * i + 2) * 32, acc);
        rank1_32(a.w, sW + (4 * i + 3) * 32, acc);
    }
    ulonglong2* op = (ulonglong2*)(out + (size_t)n * 32);
#pragma unroll
    for (int j = 0; j < 8; j++) {
        ulonglong2 t; t.x = acc[2 * j]; t.y = acc[2 * j + 1];
        op[j] = t;
    }
}

extern "C" void kernel_launch(void* const* d_in, const int* in_sizes, int n_in,
                              void* d_out, int out_size) {
    const float* h_d = (const float*)d_in[0];
    const float* h_s = (const float*)d_in[1];
    const float* ef  = (const float*)d_in[2];
    const int*   si  = (const int*)d_in[3];
    const int*   ri  = (const int*)d_in[4];
    const float* w0  = (const float*)d_in[5];
    const float* b0  = (const float*)d_in[6];
    const float* w1  = (const float*)d_in[7];
    const float* b1  = (const float*)d_in[8];
    const float* w2  = (const float*)d_in[9];
    const float* b2  = (const float*)d_in[10];
    const float* W   = (const float*)d_in[11];
    float* out = (float*)d_out;

    cudaFuncSetAttribute(edge_kernel, cudaFuncAttributeMaxDynamicSharedMemorySize,
                         SMEM_BYTES);
    cudaFuncSetAttribute(pre_kernel, cudaFuncAttributeMaxDynamicSharedMemorySize,
                         2048 * 16 + 64 * 4);

    setup_kernel<<<16, 256>>>(w0, w1, w2);
    pre_kernel<<<782, 256, 2048 * 16 + 64 * 4>>>(h_s, h_d, b0);
    edge_kernel<<<NBLK, ET, SMEM_BYTES>>>(h_d, ef, si, ri, b1, b2);
    final_kernel<<<(NN + 255) / 256, 256>>>(h_d, W, out);
}

// round 7
// speedup vs baseline: 3.4163x; 1.0806x over previous
#include <cuda_runtime.h>
#include <cstdint>

#define NN 100000
#define NE 800000
#define NBLK 148
#define ET 448          // edge kernel threads (14 warps)

typedef unsigned long long u64;
typedef unsigned int u32;

// scratch (allocation-free rule: __device__ globals)
__device__ float g_agg[NN * 32];
__device__ float g_P[NN * 64];          // fragment-major: [n][q*16 + nt*2 + c]
__device__ float g_Q[NN * 64];
__device__ ulonglong2 g_Ball[2048];     // edge weight frags (B0|B1|B2), bf16 hi|lo
__device__ ulonglong2 g_BP[2048];       // precompute weight frags (P|Q halves)

// ---------------- packed fp32x2 helpers ----------------
__device__ __forceinline__ u64 pack2(float x) {
    u64 r; asm("mov.b64 %0, {%1, %1};" : "=l"(r) : "f"(x)); return r;
}
__device__ __forceinline__ void ffma2(u64& d, u64 a, u64 b) {
    asm("fma.rn.f32x2 %0, %1, %2, %0;" : "+l"(d) : "l"(a), "l"(b));
}
// rank-1 over 16 outputs (8 u64 acc)
__device__ __forceinline__ void rank1_16(float xf, const float* w16, u64* a0) {
    u64 xa = pack2(xf);
    const ulonglong2* wr = (const ulonglong2*)w16;
#pragma unroll
    for (int j = 0; j < 4; j++) {
        ulonglong2 w = wr[j];
        ffma2(a0[2 * j],     xa, w.x);
        ffma2(a0[2 * j + 1], xa, w.y);
    }
}

// ---------------- bf16 emulation helpers ----------------
__device__ __forceinline__ u32 bf2pack(float x0, float x1) {
    u32 r;
    asm("cvt.rn.bf16x2.f32 %0, %1, %2;" : "=r"(r) : "f"(x1), "f"(x0));
    return r;
}
__device__ __forceinline__ void split_bf2(float x0, float x1, u32& h, u32& l) {
    h = bf2pack(x0, x1);
    float r0 = x0 - __uint_as_float(h << 16);
    float r1 = x1 - __uint_as_float(h & 0xFFFF0000u);
    l = bf2pack(r0, r1);
}
__device__ __forceinline__ void mma_bf(float c[4], const u32 a[4], u32 b0, u32 b1) {
    asm volatile(
        "mma.sync.aligned.m16n8k16.row.col.f32.bf16.bf16.f32 "
        "{%0,%1,%2,%3}, {%4,%5,%6,%7}, {%8,%9}, {%0,%1,%2,%3};"
        : "+f"(c[0]), "+f"(c[1]), "+f"(c[2]), "+f"(c[3])
        : "r"(a[0]), "r"(a[1]), "r"(a[2]), "r"(a[3]), "r"(b0), "r"(b1));
}
template <int NTC>
__device__ __forceinline__ void gemm_step(float C[][4], const u32 ah[4], const u32 al[4],
                                          const ulonglong2* sB, int kc, int Kc, int lane) {
    u32 bh[NTC][2], bl[NTC][2];
#pragma unroll
    for (int nt = 0; nt < NTC; nt++) {
        ulonglong2 t = sB[(nt * Kc + kc) * 32 + lane];
        bh[nt][0] = (u32)t.x; bl[nt][0] = (u32)(t.x >> 32);
        bh[nt][1] = (u32)t.y; bl[nt][1] = (u32)(t.y >> 32);
    }
#pragma unroll
    for (int nt = 0; nt < NTC; nt++) mma_bf(C[nt], ah, bh[nt][0], bh[nt][1]);
#pragma unroll
    for (int nt = 0; nt < NTC; nt++) mma_bf(C[nt], ah, bl[nt][0], bl[nt][1]);
#pragma unroll
    for (int nt = 0; nt < NTC; nt++) mma_bf(C[nt], al, bh[nt][0], bh[nt][1]);
}
__device__ __forceinline__ void build_a(const float cA[4], const float cB[4],
                                        u32 ah[4], u32 al[4]) {
    split_bf2(fmaxf(cA[0], 0.f), fmaxf(cA[1], 0.f), ah[0], al[0]);
    split_bf2(fmaxf(cA[2], 0.f), fmaxf(cA[3], 0.f), ah[1], al[1]);
    split_bf2(fmaxf(cB[0], 0.f), fmaxf(cB[1], 0.f), ah[2], al[2]);
    split_bf2(fmaxf(cB[2], 0.f), fmaxf(cB[3], 0.f), ah[3], al[3]);
}
__device__ __forceinline__ void red2(float* p, float x, float y) {
    asm volatile("red.global.add.v2.f32 [%0], {%1,%2};" :: "l"(p), "f"(x), "f"(y) : "memory");
}

// ---------------- setup: natural-order bf16 hi|lo weight fragments ----------------
__global__ void setup_kernel(const float* __restrict__ w0, const float* __restrict__ w1,
                             const float* __restrict__ w2) {
    int i = blockIdx.x * 256 + threadIdx.x;
    if (i >= 4096) return;
    int lane = i & 31, f = i >> 5;
    int g = lane >> 2, q = lane & 3;
    float v00, v01, v10, v11;
    if (f < 64) {
        const float* W; int nidx, k0, stride;
        if (f < 16)      { int nt = f >> 1,  kc = f & 1;  W = w0 + 128 * 64; stride = 64; nidx = nt * 8 + g; k0 = 16 * kc + 2 * q; }
        else if (f < 48) { int ff = f - 16; int nt = ff >> 2, kc = ff & 3; W = w1; stride = 64; nidx = nt * 8 + g; k0 = 16 * kc + 2 * q; }
        else             { int ff = f - 48; int nt = ff >> 2, kc = ff & 3; W = w2; stride = 32; nidx = nt * 8 + g; k0 = 16 * kc + 2 * q; }
        v00 = W[(size_t)k0 * stride + nidx];
        v01 = W[(size_t)(k0 + 1) * stride + nidx];
        v10 = W[(size_t)(k0 + 8) * stride + nidx];
        v11 = W[(size_t)(k0 + 9) * stride + nidx];
    } else {
        int ff = f - 64;
        int nt = ff >> 2, kc = ff & 3;
        int isq = (nt >= 8) ? 32 : 0;
        int nidx = (nt & 7) * 8 + g;
        int k0 = 16 * kc + 2 * q;
        int r00 = ((k0     < 32) ? k0     : k0 + 32) + isq;
        int r01 = ((k0 + 1 < 32) ? k0 + 1 : k0 + 33) + isq;
        int r10 = ((k0 + 8 < 32) ? k0 + 8 : k0 + 40) + isq;
        int r11 = ((k0 + 9 < 32) ? k0 + 9 : k0 + 41) + isq;
        v00 = w0[(size_t)r00 * 64 + nidx];
        v01 = w0[(size_t)r01 * 64 + nidx];
        v10 = w0[(size_t)r10 * 64 + nidx];
        v11 = w0[(size_t)r11 * 64 + nidx];
    }
    u32 h0, l0, h1, l1;
    split_bf2(v00, v01, h0, l0);
    split_bf2(v10, v11, h1, l1);
    ulonglong2 t;
    t.x = (u64)h0 | ((u64)l0 << 32);
    t.y = (u64)h1 | ((u64)l1 << 32);
    if (f < 64) g_Ball[i] = t; else g_BP[i - 2048] = t;
}

// ---------------- precompute: P|Q = [h_s|h_d] @ W' via bf16 MMA; zeros g_agg ----------------
__global__ void __launch_bounds__(256, 1)
pre_kernel(const float* __restrict__ h_s, const float* __restrict__ h_d,
           const float* __restrict__ b0) {
    extern __shared__ ulonglong2 smem_v2[];
    float* s_b0 = (float*)(smem_v2 + 2048);
    const int tid = threadIdx.x, wid = tid >> 5, lane = tid & 31;
    const int g = lane >> 2, q = lane & 3;
    for (int i = tid; i < 2048; i += 256) smem_v2[i] = g_BP[i];
    if (tid < 64) s_b0[tid] = b0[tid];
    __syncthreads();

    int n0 = (blockIdx.x * 8 + wid) * 16;
    if (n0 >= NN) return;

    float C[16][4];
#pragma unroll
    for (int nt = 0; nt < 8; nt++) {
        C[nt][0] = 0.f; C[nt][1] = 0.f; C[nt][2] = 0.f; C[nt][3] = 0.f;
        float b0v = s_b0[nt * 8 + 2 * q], b1v = s_b0[nt * 8 + 2 * q + 1];
        C[8 + nt][0] = b0v; C[8 + nt][1] = b1v; C[8 + nt][2] = b0v; C[8 + nt][3] = b1v;
    }
#pragma unroll
    for (int kc = 0; kc < 4; kc++) {
        const float* src = (kc < 2) ? h_s : h_d;
        int off = (kc & 1) * 16 + 2 * q;
        float2 x0 = *(const float2*)(src + (size_t)(n0 + g) * 32 + off);
        float2 x1 = *(const float2*)(src + (size_t)(n0 + 8 + g) * 32 + off);
        float2 x2 = *(const float2*)(src + (size_t)(n0 + g) * 32 + off + 8);
        float2 x3 = *(const float2*)(src + (size_t)(n0 + 8 + g) * 32 + off + 8);
        u32 ah[4], al[4];
        split_bf2(x0.x, x0.y, ah[0], al[0]);
        split_bf2(x1.x, x1.y, ah[1], al[1]);
        split_bf2(x2.x, x2.y, ah[2], al[2]);
        split_bf2(x3.x, x3.y, ah[3], al[3]);
        gemm_step<8>(C,     ah, al, smem_v2,           kc, 4, lane);   // P
        gemm_step<8>(C + 8, ah, al, smem_v2 + 32 * 32, kc, 4, lane);   // Q
    }
#pragma unroll
    for (int j = 0; j < 4; j++) {
        *(float4*)(g_P + (size_t)(n0 + g)     * 64 + q * 16 + 4 * j) =
            make_float4(C[2*j][0], C[2*j][1], C[2*j+1][0], C[2*j+1][1]);
        *(float4*)(g_P + (size_t)(n0 + 8 + g) * 64 + q * 16 + 4 * j) =
            make_float4(C[2*j][2], C[2*j][3], C[2*j+1][2], C[2*j+1][3]);
        *(float4*)(g_Q + (size_t)(n0 + g)     * 64 + q * 16 + 4 * j) =
            make_float4(C[8+2*j][0], C[8+2*j][1], C[8+2*j+1][0], C[8+2*j+1][1]);
        *(float4*)(g_Q + (size_t)(n0 + 8 + g) * 64 + q * 16 + 4 * j) =
            make_float4(C[8+2*j][2], C[8+2*j][3], C[8+2*j+1][2], C[8+2*j+1][3]);
    }
    float4 z = make_float4(0.f, 0.f, 0.f, 0.f);
    float4* ag = (float4*)(g_agg + (size_t)n0 * 32);
#pragma unroll
    for (int i = 0; i < 4; i++) ag[lane + 32 * i] = z;
}

// ---------------- edge kernel: bf16 MMA MLP ----------------
#define SMEM_BYTES (2048 * 16 + 96 * 4)

__global__ void __launch_bounds__(ET, 1)
edge_kernel(const float* __restrict__ h_d, const float* __restrict__ ef,
            const int* __restrict__ si, const int* __restrict__ ri,
            const float* __restrict__ b1, const float* __restrict__ b2) {
    extern __shared__ ulonglong2 smem_v2[];
    ulonglong2* sB0 = smem_v2;           // 16 frags
    ulonglong2* sB1 = smem_v2 + 512;     // 32 frags
    ulonglong2* sB2 = smem_v2 + 1536;    // 16 frags
    float* s_b1 = (float*)(smem_v2 + 2048);
    float* s_b2 = s_b1 + 64;

    const int tid = threadIdx.x, wid = tid >> 5, lane = tid & 31;
    for (int i = tid; i < 2048; i += ET) smem_v2[i] = g_Ball[i];
    if (tid < 64) s_b1[tid] = b1[tid];
    if (tid < 32) s_b2[tid] = b2[tid];
    __syncthreads();

    const int g = lane >> 2, q = lane & 3;
    const int col2 = 2 * q;
    const int WPC = ET / 32;            // warps per CTA

#pragma unroll 1
    for (int base = blockIdx.x * (WPC * 16) + wid * 16; base < NE; base += NBLK * (WPC * 16)) {
        int e0 = base + g, e1 = base + 8 + g;
        bool v0 = e0 < NE, v1 = e1 < NE;
        int e0c = v0 ? e0 : NE - 1;
        int e1c = v1 ? e1 : NE - 1;
        int s0 = si[e0c], rc0 = ri[e0c];
        int s1 = si[e1c], rc1 = ri[e1c];

        // ===== layer 0: C init from P[s]+Q[r] =====
        float C[8][4];
        {
            const float4* P0 = (const float4*)(g_P + (size_t)s0  * 64 + q * 16);
            const float4* Q0 = (const float4*)(g_Q + (size_t)rc0 * 64 + q * 16);
            const float4* P1 = (const float4*)(g_P + (size_t)s1  * 64 + q * 16);
            const float4* Q1 = (const float4*)(g_Q + (size_t)rc1 * 64 + q * 16);
#pragma unroll
            for (int j = 0; j < 4; j++) {
                float4 p = P0[j], qq = Q0[j];
                C[2*j][0]   = p.x + qq.x; C[2*j][1]   = p.y + qq.y;
                C[2*j+1][0] = p.z + qq.z; C[2*j+1][1] = p.w + qq.w;
                p = P1[j]; qq = Q1[j];
                C[2*j][2]   = p.x + qq.x; C[2*j][3]   = p.y + qq.y;
                C[2*j+1][2] = p.z + qq.z; C[2*j+1][3] = p.w + qq.w;
            }
        }
        // ===== layer 0: += ef @ W0e =====
#pragma unroll
        for (int kc = 0; kc < 2; kc++) {
            int off = 16 * kc + col2;
            float2 x0 = *(const float2*)(ef + (size_t)e0c * 32 + off);
            float2 x1 = *(const float2*)(ef + (size_t)e1c * 32 + off);
            float2 x2 = *(const float2*)(ef + (size_t)e0c * 32 + off + 8);
            float2 x3 = *(const float2*)(ef + (size_t)e1c * 32 + off + 8);
            u32 ah[4], al[4];
            split_bf2(x0.x, x0.y, ah[0], al[0]);
            split_bf2(x1.x, x1.y, ah[1], al[1]);
            split_bf2(x2.x, x2.y, ah[2], al[2]);
            split_bf2(x3.x, x3.y, ah[3], al[3]);
            gemm_step<8>(C, ah, al, sB0, kc, 2, lane);
        }

        // ===== layer 1 =====
        float C1[8][4];
#pragma unroll
        for (int nt = 0; nt < 8; nt++) {
            float bb0 = s_b1[nt * 8 + col2], bb1 = s_b1[nt * 8 + col2 + 1];
            C1[nt][0] = bb0; C1[nt][1] = bb1; C1[nt][2] = bb0; C1[nt][3] = bb1;
        }
#pragma unroll
        for (int kc = 0; kc < 4; kc++) {
            u32 ah[4], al[4];
            build_a(C[2 * kc], C[2 * kc + 1], ah, al);
            gemm_step<8>(C1, ah, al, sB1, kc, 4, lane);
        }

        // ===== layer 2 =====
        float C2[4][4];
#pragma unroll
        for (int nt = 0; nt < 4; nt++) {
            float bb0 = s_b2[nt * 8 + col2], bb1 = s_b2[nt * 8 + col2 + 1];
            C2[nt][0] = bb0; C2[nt][1] = bb1; C2[nt][2] = bb0; C2[nt][3] = bb1;
        }
#pragma unroll
        for (int kc = 0; kc < 4; kc++) {
            u32 ah[4], al[4];
            build_a(C1[2 * kc], C1[2 * kc + 1], ah, al);
            gemm_step<4>(C2, ah, al, sB2, kc, 4, lane);
        }

        // ===== epilogue =====
#pragma unroll
        for (int nt = 0; nt < 4; nt++) {
            int cc = nt * 8 + col2;
            if (v0) {
                float2 dj = *(const float2*)(h_d + (size_t)rc0 * 32 + cc);
                float2 di = *(const float2*)(h_d + (size_t)s0 * 32 + cc);
                red2(g_agg + (size_t)rc0 * 32 + cc,
                     fmaxf(C2[nt][0], 0.f) * (dj.x - di.x),
                     fmaxf(C2[nt][1], 0.f) * (dj.y - di.y));
            }
            if (v1) {
                float2 dj = *(const float2*)(h_d + (size_t)rc1 * 32 + cc);
                float2 di = *(const float2*)(h_d + (size_t)s1 * 32 + cc);
                red2(g_agg + (size_t)rc1 * 32 + cc,
                     fmaxf(C2[nt][2], 0.f) * (dj.x - di.x),
                     fmaxf(C2[nt][3], 0.f) * (dj.y - di.y));
            }
        }
    }
}

// out[n] = h_d_prev[n] + agg[n] @ W   (2 threads per node, 16 outputs each)
__global__ void __launch_bounds__(256)
final_kernel(const float* __restrict__ h_d, const float* __restrict__ W,
             float* __restrict__ out) {
    __shared__ float sW[1024];
    int tid = threadIdx.x;
    {
        float4* d4 = (float4*)sW;
        const float4* s4 = (const float4*)W;
        for (int i = tid; i < 256; i += 256) d4[i] = s4[i];
    }
    __syncthreads();
    int idx = blockIdx.x * 256 + tid;
    int n = idx >> 1, half = idx & 1;
    if (n >= NN) return;

    u64 acc[8];
    {
        const ulonglong2* hp = (const ulonglong2*)(h_d + (size_t)n * 32 + half * 16);
#pragma unroll
        for (int j = 0; j < 4; j++) {
            ulonglong2 t = hp[j];
            acc[2 * j] = t.x; acc[2 * j + 1] = t.y;
        }
    }
    const float4* ap = (const float4*)(g_agg + (size_t)n * 32);
    const float* wb = sW + half * 16;
#pragma unroll
    for (int i = 0; i < 8; i++) {
        float4 a = ap[i];
        rank1_16(a.x, wb + (4 * i) * 32,     acc);
        rank1_16(a.y, wb + (4 * i + 1) * 32, acc);
        rank1_16(a.z, wb + (4 * i + 2) * 32, acc);
        rank1_16(a.w, wb + (4 * i + 3) * 32, acc);
    }
    ulonglong2* op = (ulonglong2*)(out + (size_t)n * 32 + half * 16);
#pragma unroll
    for (int j = 0; j < 4; j++) {
        ulonglong2 t; t.x = acc[2 * j]; t.y = acc[2 * j + 1];
        op[j] = t;
    }
}

extern "C" void kernel_launch(void* const* d_in, const int* in_sizes, int n_in,
                              void* d_out, int out_size) {
    const float* h_d = (const float*)d_in[0];
    const float* h_s = (const float*)d_in[1];
    const float* ef  = (const float*)d_in[2];
    const int*   si  = (const int*)d_in[3];
    const int*   ri  = (const int*)d_in[4];
    const float* w0  = (const float*)d_in[5];
    const float* b0  = (const float*)d_in[6];
    const float* w1  = (const float*)d_in[7];
    const float* b1  = (const float*)d_in[8];
    const float* w2  = (const float*)d_in[9];
    const float* b2  = (const float*)d_in[10];
    const float* W   = (const float*)d_in[11];
    float* out = (float*)d_out;

    cudaFuncSetAttribute(edge_kernel, cudaFuncAttributeMaxDynamicSharedMemorySize,
                         SMEM_BYTES);
    cudaFuncSetAttribute(pre_kernel, cudaFuncAttributeMaxDynamicSharedMemorySize,
                         2048 * 16 + 64 * 4);

    setup_kernel<<<16, 256>>>(w0, w1, w2);
    pre_kernel<<<782, 256, 2048 * 16 + 64 * 4>>>(h_s, h_d, b0);
    edge_kernel<<<NBLK, ET, SMEM_BYTES>>>(h_d, ef, si, ri, b1, b2);
    final_kernel<<<(2 * NN + 255) / 256, 256>>>(h_d, W, out);
}